// round 7
// baseline (speedup 1.0000x reference)
#include <cuda_runtime.h>

// EdgewiseReduce: out[n, :] = sum_{e : edge_center[e] == n} edge_feat[e, :]
// edge_center (= edge_index[0]) is SORTED ascending.
//
// Pass 1 (build_offsets): vectorized (4 keys/thread) CSR row_offsets;
//   prev-key via __shfl_up (lane 0 loads one extra scalar).
// Pass 2 (reduce): PERSISTENT WARPS. Fixed chip-filling grid; each warp owns a
//   contiguous run of nodes (~11), so per-warp work is a sum of ~11 Poisson
//   degrees (tight spread) and warp slots never fragment at CTA granularity.
//   Per node: lanes 0-15 / 16-31 hold two edges' float4 rows (512B/warp/step),
//   8 predicated steps in flight, final 16-wide shfl combine, one 256B store.
//   Consecutive nodes share an offset load (end(n) == start(n+1)).
//   No atomics, no memset.
//
// Inputs (metadata order):
//   d_in[0] = edge_index  [2, E]  int64 (or int32; runtime-detected)
//   d_in[1] = edge_feat   [E, 64] float32
//   d_in[2] = node_types  [N, 1]
// Output: [N, 64] float32

#define D_FEAT 64
#define LANES 16
#define BLOCK_THREADS 256
#define WARPS_PER_BLOCK (BLOCK_THREADS / 32)
#define KEYS_PER_THREAD 4
#define STEPS 8                     // edges per inner iter = 2 * STEPS = 16
#define TARGET_CTAS 592             // ~148 SMs x 4 CTAs
#define MAX_NODES_P1 (1 << 21)

__device__ int g_offsets[MAX_NODES_P1];

// ---------------- Pass 1: CSR offsets from sorted keys ---------------------
__global__ void __launch_bounds__(256)
build_offsets_kernel(const void* __restrict__ edge_index, int E, int N)
{
    // dtype detection: an int64 read of an int32 buffer fuses two indices ->
    // value >= 2^32 >> N with overwhelming probability across 3 probes.
    __shared__ int s_is64;
    if (threadIdx.x == 0) {
        const long long* q = (const long long*)edge_index;
        unsigned long long v0 = (unsigned long long)q[E / 3];
        unsigned long long v1 = (unsigned long long)q[E / 2];
        unsigned long long v2 = (unsigned long long)q[E - 1];
        unsigned long long nn = (unsigned long long)N;
        s_is64 = (v0 < nn && v1 < nn && v2 < nn) ? 1 : 0;
    }
    __syncthreads();
    const bool is64 = (s_is64 != 0);

    const long long* __restrict__ p64 = (const long long*)edge_index;
    const int*       __restrict__ p32 = (const int*)edge_index;

    const int base = (blockIdx.x * blockDim.x + threadIdx.x) * KEYS_PER_THREAD;
    const int lane = threadIdx.x & 31;

    int k[KEYS_PER_THREAD];
    int nvalid = 0;
    if (base < E) {
        if (base + KEYS_PER_THREAD <= E) {
            nvalid = KEYS_PER_THREAD;
            if (is64) {
                longlong2 v0 = ((const longlong2*)p64)[(base >> 1) + 0];
                longlong2 v1 = ((const longlong2*)p64)[(base >> 1) + 1];
                k[0] = (int)v0.x; k[1] = (int)v0.y; k[2] = (int)v1.x; k[3] = (int)v1.y;
            } else {
                int4 v = ((const int4*)p32)[base >> 2];
                k[0] = v.x; k[1] = v.y; k[2] = v.z; k[3] = v.w;
            }
        } else {
            nvalid = E - base;
            #pragma unroll
            for (int j = 0; j < KEYS_PER_THREAD; ++j)
                if (j < nvalid) k[j] = is64 ? (int)p64[base + j] : p32[base + j];
        }
    }
    for (int j = nvalid; j < KEYS_PER_THREAD; ++j) k[j] = 0;  // shfl payload

    int prev = __shfl_up_sync(0xffffffffu, k[KEYS_PER_THREAD - 1], 1);
    if (lane == 0 && base > 0 && base <= E)
        prev = is64 ? (int)p64[base - 1] : p32[base - 1];
    if (base == 0) prev = -1;

    if (base >= E) return;

    #pragma unroll
    for (int j = 0; j < KEYS_PER_THREAD; ++j) {
        if (j < nvalid) {
            const int c = k[j];
            for (int n = prev + 1; n <= c; ++n) g_offsets[n] = base + j;
            prev = c;
        }
    }

    if (base + nvalid == E) {
        for (int n = prev + 1; n <= N; ++n) g_offsets[n] = E;
    }
}

// ---------------- Pass 2: persistent warps, contiguous node runs -----------
__global__ void __launch_bounds__(BLOCK_THREADS)
edgewise_reduce_kernel(const float4* __restrict__ feat,   // [E * LANES]
                       float4* __restrict__ out,          // [N * LANES]
                       int N, int nodes_per_warp)
{
    const int lane  = threadIdx.x & 31;
    const int sub   = lane >> 4;        // which edge of the pair (0/1)
    const int flane = lane & (LANES - 1);
    const int gwarp = blockIdx.x * WARPS_PER_BLOCK + (threadIdx.x >> 5);

    const int node0 = gwarp * nodes_per_warp;
    if (node0 >= N) return;
    const int node1 = min(node0 + nodes_per_warp, N);

    int start = g_offsets[node0];

    for (int node = node0; node < node1; ++node) {
        const int end = g_offsets[node + 1];

        float4 acc = make_float4(0.f, 0.f, 0.f, 0.f);

        #pragma unroll 1
        for (int e = start + sub; e < end; e += 2 * STEPS) {
            // 8 independent predicated LDG.128 per thread (128B in flight).
            #pragma unroll
            for (int i = 0; i < STEPS; ++i) {
                const int idx = e + 2 * i;
                if (idx < end) {
                    float4 v = __ldg(&feat[(long long)idx * LANES + flane]);
                    acc.x += v.x; acc.y += v.y; acc.z += v.z; acc.w += v.w;
                }
            }
        }

        // Combine the two edge-halves: lane l += lane l+16.
        acc.x += __shfl_down_sync(0xffffffffu, acc.x, 16);
        acc.y += __shfl_down_sync(0xffffffffu, acc.y, 16);
        acc.z += __shfl_down_sync(0xffffffffu, acc.z, 16);
        acc.w += __shfl_down_sync(0xffffffffu, acc.w, 16);

        if (sub == 0)
            out[(long long)node * LANES + flane] = acc;

        start = end;   // next node's range begins where this one ended
    }
}

extern "C" void kernel_launch(void* const* d_in, const int* in_sizes, int n_in,
                              void* d_out, int out_size)
{
    const void*   edge_index = d_in[0];
    const float4* feat       = (const float4*)d_in[1];
    float4*       out        = (float4*)d_out;

    const int E = in_sizes[1] / D_FEAT;
    const int N = out_size / D_FEAT;

    const int p1_threads = (E + KEYS_PER_THREAD - 1) / KEYS_PER_THREAD;
    build_offsets_kernel<<<(p1_threads + 255) / 256, 256>>>(edge_index, E, N);

    // Size node runs so the grid is ~TARGET_CTAS persistent CTAs.
    const int total_warps_target = TARGET_CTAS * WARPS_PER_BLOCK;
    int npw = (N + total_warps_target - 1) / total_warps_target;
    if (npw < 1) npw = 1;
    const int warps_needed = (N + npw - 1) / npw;
    const int grid = (warps_needed + WARPS_PER_BLOCK - 1) / WARPS_PER_BLOCK;

    edgewise_reduce_kernel<<<grid, BLOCK_THREADS>>>(feat, out, N, npw);
}

// round 8
// speedup vs baseline: 1.0538x; 1.0538x over previous
#include <cuda_runtime.h>

// EdgewiseReduce: out[n, :] = sum_{e : edge_center[e] == n} edge_feat[e, :]
// edge_center (= edge_index[0]) is SORTED ascending.
//
// Pass 1 (build_offsets): vectorized (4 keys/thread) CSR row_offsets;
//   prev-key via __shfl_up (lane 0 loads one extra scalar).
// Pass 2 (reduce): single-wave persistent warps, grid sized for FULL warp-slot
//   residency (~1184 CTAs = 8 CTAs/SM). Each warp owns ~6 contiguous nodes:
//   per-warp work = sum of ~6 Poisson degrees (±10%), sequential feat
//   streaming, one offset load per node (end(n) == start(n+1)).
//   Per node: lanes 0-15 / 16-31 hold two edges' float4 rows (512B/warp/step),
//   8 predicated steps in flight (128B/thread), 16-wide shfl combine, one
//   coalesced 256B store. No atomics, no memset.
//
// Inputs (metadata order):
//   d_in[0] = edge_index  [2, E]  int64 (or int32; runtime-detected)
//   d_in[1] = edge_feat   [E, 64] float32
//   d_in[2] = node_types  [N, 1]
// Output: [N, 64] float32

#define D_FEAT 64
#define LANES 16
#define BLOCK_THREADS 256
#define WARPS_PER_BLOCK (BLOCK_THREADS / 32)
#define KEYS_PER_THREAD 4
#define STEPS 8                     // edges per inner iter = 2 * STEPS = 16
#define TARGET_CTAS 1184            // 148 SMs x 8 CTAs -> 64 warps/SM residency
#define MAX_NODES_P1 (1 << 21)

__device__ int g_offsets[MAX_NODES_P1];

// ---------------- Pass 1: CSR offsets from sorted keys ---------------------
__global__ void __launch_bounds__(256)
build_offsets_kernel(const void* __restrict__ edge_index, int E, int N)
{
    // dtype detection: an int64 read of an int32 buffer fuses two indices ->
    // value >= 2^32 >> N with overwhelming probability across 3 probes.
    __shared__ int s_is64;
    if (threadIdx.x == 0) {
        const long long* q = (const long long*)edge_index;
        unsigned long long v0 = (unsigned long long)q[E / 3];
        unsigned long long v1 = (unsigned long long)q[E / 2];
        unsigned long long v2 = (unsigned long long)q[E - 1];
        unsigned long long nn = (unsigned long long)N;
        s_is64 = (v0 < nn && v1 < nn && v2 < nn) ? 1 : 0;
    }
    __syncthreads();
    const bool is64 = (s_is64 != 0);

    const long long* __restrict__ p64 = (const long long*)edge_index;
    const int*       __restrict__ p32 = (const int*)edge_index;

    const int base = (blockIdx.x * blockDim.x + threadIdx.x) * KEYS_PER_THREAD;
    const int lane = threadIdx.x & 31;

    int k[KEYS_PER_THREAD];
    int nvalid = 0;
    if (base < E) {
        if (base + KEYS_PER_THREAD <= E) {
            nvalid = KEYS_PER_THREAD;
            if (is64) {
                longlong2 v0 = ((const longlong2*)p64)[(base >> 1) + 0];
                longlong2 v1 = ((const longlong2*)p64)[(base >> 1) + 1];
                k[0] = (int)v0.x; k[1] = (int)v0.y; k[2] = (int)v1.x; k[3] = (int)v1.y;
            } else {
                int4 v = ((const int4*)p32)[base >> 2];
                k[0] = v.x; k[1] = v.y; k[2] = v.z; k[3] = v.w;
            }
        } else {
            nvalid = E - base;
            #pragma unroll
            for (int j = 0; j < KEYS_PER_THREAD; ++j)
                if (j < nvalid) k[j] = is64 ? (int)p64[base + j] : p32[base + j];
        }
    }
    for (int j = nvalid; j < KEYS_PER_THREAD; ++j) k[j] = 0;  // shfl payload

    int prev = __shfl_up_sync(0xffffffffu, k[KEYS_PER_THREAD - 1], 1);
    if (lane == 0 && base > 0 && base <= E)
        prev = is64 ? (int)p64[base - 1] : p32[base - 1];
    if (base == 0) prev = -1;

    if (base >= E) return;

    #pragma unroll
    for (int j = 0; j < KEYS_PER_THREAD; ++j) {
        if (j < nvalid) {
            const int c = k[j];
            for (int n = prev + 1; n <= c; ++n) g_offsets[n] = base + j;
            prev = c;
        }
    }

    if (base + nvalid == E) {
        for (int n = prev + 1; n <= N; ++n) g_offsets[n] = E;
    }
}

// ---------------- Pass 2: residency-filling persistent warps ---------------
__global__ void __launch_bounds__(BLOCK_THREADS)
edgewise_reduce_kernel(const float4* __restrict__ feat,   // [E * LANES]
                       float4* __restrict__ out,          // [N * LANES]
                       int N, int nodes_per_warp)
{
    const int lane  = threadIdx.x & 31;
    const int sub   = lane >> 4;        // which edge of the pair (0/1)
    const int flane = lane & (LANES - 1);
    const int gwarp = blockIdx.x * WARPS_PER_BLOCK + (threadIdx.x >> 5);

    const int node0 = gwarp * nodes_per_warp;
    if (node0 >= N) return;
    const int node1 = min(node0 + nodes_per_warp, N);

    int start = g_offsets[node0];

    for (int node = node0; node < node1; ++node) {
        const int end = g_offsets[node + 1];

        float4 acc = make_float4(0.f, 0.f, 0.f, 0.f);

        #pragma unroll 1
        for (int e = start + sub; e < end; e += 2 * STEPS) {
            // 8 independent predicated LDG.128 per thread (128B in flight).
            #pragma unroll
            for (int i = 0; i < STEPS; ++i) {
                const int idx = e + 2 * i;
                if (idx < end) {
                    float4 v = __ldg(&feat[(long long)idx * LANES + flane]);
                    acc.x += v.x; acc.y += v.y; acc.z += v.z; acc.w += v.w;
                }
            }
        }

        // Combine the two edge-halves: lane l += lane l+16.
        acc.x += __shfl_down_sync(0xffffffffu, acc.x, 16);
        acc.y += __shfl_down_sync(0xffffffffu, acc.y, 16);
        acc.z += __shfl_down_sync(0xffffffffu, acc.z, 16);
        acc.w += __shfl_down_sync(0xffffffffu, acc.w, 16);

        if (sub == 0)
            out[(long long)node * LANES + flane] = acc;

        start = end;   // next node's range begins where this one ended
    }
}

extern "C" void kernel_launch(void* const* d_in, const int* in_sizes, int n_in,
                              void* d_out, int out_size)
{
    const void*   edge_index = d_in[0];
    const float4* feat       = (const float4*)d_in[1];
    float4*       out        = (float4*)d_out;

    const int E = in_sizes[1] / D_FEAT;
    const int N = out_size / D_FEAT;

    const int p1_threads = (E + KEYS_PER_THREAD - 1) / KEYS_PER_THREAD;
    build_offsets_kernel<<<(p1_threads + 255) / 256, 256>>>(edge_index, E, N);

    // Size node runs so the grid fills warp-slot residency in ONE wave:
    // ~1184 CTAs (8 CTAs/SM x 148 SMs) x 8 warps.
    const int total_warps_target = TARGET_CTAS * WARPS_PER_BLOCK;
    int npw = (N + total_warps_target - 1) / total_warps_target;
    if (npw < 1) npw = 1;
    const int warps_needed = (N + npw - 1) / npw;
    const int grid = (warps_needed + WARPS_PER_BLOCK - 1) / WARPS_PER_BLOCK;

    edgewise_reduce_kernel<<<grid, BLOCK_THREADS>>>(feat, out, N, npw);
}

// round 9
// speedup vs baseline: 1.1411x; 1.0828x over previous
#include <cuda_runtime.h>

// EdgewiseReduce: out[n, :] = sum_{e : edge_center[e] == n} edge_feat[e, :]
// edge_center (= edge_index[0]) is SORTED ascending.
//
// Pass 1 (build_offsets): vectorized (4 keys/thread) CSR row_offsets;
//   prev-key via __shfl_up (lane 0 loads one extra scalar).
// Pass 2 (reduce): ONE WARP PER NODE, SMALL CTAs (64 threads = 2 warps) so CTA
//   retire granularity tracks max of 2 (not 8) i.i.d. node degrees -> minimal
//   warp-slot waste at wave transitions while keeping the best-measured inner
//   loop: lanes 0-15 / 16-31 hold two edges' float4 rows (512B/warp/step),
//   8 predicated steps in flight (128B/thread), 16-wide shfl combine, one
//   coalesced 256B store. No atomics, no memset, no inter-node serialization.
//
// Inputs (metadata order):
//   d_in[0] = edge_index  [2, E]  int64 (or int32; runtime-detected)
//   d_in[1] = edge_feat   [E, 64] float32
//   d_in[2] = node_types  [N, 1]
// Output: [N, 64] float32

#define D_FEAT 64
#define LANES 16
#define BLOCK_THREADS 64                       // 2 warps per CTA
#define WARPS_PER_BLOCK (BLOCK_THREADS / 32)
#define KEYS_PER_THREAD 4
#define STEPS 8                     // edges per inner iter = 2 * STEPS = 16
#define MAX_NODES_P1 (1 << 21)

__device__ int g_offsets[MAX_NODES_P1];

// ---------------- Pass 1: CSR offsets from sorted keys ---------------------
__global__ void __launch_bounds__(256)
build_offsets_kernel(const void* __restrict__ edge_index, int E, int N)
{
    // dtype detection: an int64 read of an int32 buffer fuses two indices ->
    // value >= 2^32 >> N with overwhelming probability across 3 probes.
    __shared__ int s_is64;
    if (threadIdx.x == 0) {
        const long long* q = (const long long*)edge_index;
        unsigned long long v0 = (unsigned long long)q[E / 3];
        unsigned long long v1 = (unsigned long long)q[E / 2];
        unsigned long long v2 = (unsigned long long)q[E - 1];
        unsigned long long nn = (unsigned long long)N;
        s_is64 = (v0 < nn && v1 < nn && v2 < nn) ? 1 : 0;
    }
    __syncthreads();
    const bool is64 = (s_is64 != 0);

    const long long* __restrict__ p64 = (const long long*)edge_index;
    const int*       __restrict__ p32 = (const int*)edge_index;

    const int base = (blockIdx.x * blockDim.x + threadIdx.x) * KEYS_PER_THREAD;
    const int lane = threadIdx.x & 31;

    int k[KEYS_PER_THREAD];
    int nvalid = 0;
    if (base < E) {
        if (base + KEYS_PER_THREAD <= E) {
            nvalid = KEYS_PER_THREAD;
            if (is64) {
                longlong2 v0 = ((const longlong2*)p64)[(base >> 1) + 0];
                longlong2 v1 = ((const longlong2*)p64)[(base >> 1) + 1];
                k[0] = (int)v0.x; k[1] = (int)v0.y; k[2] = (int)v1.x; k[3] = (int)v1.y;
            } else {
                int4 v = ((const int4*)p32)[base >> 2];
                k[0] = v.x; k[1] = v.y; k[2] = v.z; k[3] = v.w;
            }
        } else {
            nvalid = E - base;
            #pragma unroll
            for (int j = 0; j < KEYS_PER_THREAD; ++j)
                if (j < nvalid) k[j] = is64 ? (int)p64[base + j] : p32[base + j];
        }
    }
    for (int j = nvalid; j < KEYS_PER_THREAD; ++j) k[j] = 0;  // shfl payload

    int prev = __shfl_up_sync(0xffffffffu, k[KEYS_PER_THREAD - 1], 1);
    if (lane == 0 && base > 0 && base <= E)
        prev = is64 ? (int)p64[base - 1] : p32[base - 1];
    if (base == 0) prev = -1;

    if (base >= E) return;

    #pragma unroll
    for (int j = 0; j < KEYS_PER_THREAD; ++j) {
        if (j < nvalid) {
            const int c = k[j];
            for (int n = prev + 1; n <= c; ++n) g_offsets[n] = base + j;
            prev = c;
        }
    }

    if (base + nvalid == E) {
        for (int n = prev + 1; n <= N; ++n) g_offsets[n] = E;
    }
}

// ---------------- Pass 2: warp-per-node, 2-warp CTAs ------------------------
__global__ void __launch_bounds__(BLOCK_THREADS)
edgewise_reduce_kernel(const float4* __restrict__ feat,   // [E * LANES]
                       float4* __restrict__ out,          // [N * LANES]
                       int N)
{
    const int lane  = threadIdx.x & 31;
    const int sub   = lane >> 4;        // which edge of the pair (0/1)
    const int flane = lane & (LANES - 1);
    const int node  = blockIdx.x * WARPS_PER_BLOCK + (threadIdx.x >> 5);
    if (node >= N) return;

    const int start = g_offsets[node];
    const int end   = g_offsets[node + 1];

    float4 acc = make_float4(0.f, 0.f, 0.f, 0.f);

    #pragma unroll 1
    for (int e = start + sub; e < end; e += 2 * STEPS) {
        // 8 independent predicated LDG.128 per thread (128B in flight).
        #pragma unroll
        for (int i = 0; i < STEPS; ++i) {
            const int idx = e + 2 * i;
            if (idx < end) {
                float4 v = __ldg(&feat[(long long)idx * LANES + flane]);
                acc.x += v.x; acc.y += v.y; acc.z += v.z; acc.w += v.w;
            }
        }
    }

    // Combine the two edge-halves: lane l += lane l+16.
    acc.x += __shfl_down_sync(0xffffffffu, acc.x, 16);
    acc.y += __shfl_down_sync(0xffffffffu, acc.y, 16);
    acc.z += __shfl_down_sync(0xffffffffu, acc.z, 16);
    acc.w += __shfl_down_sync(0xffffffffu, acc.w, 16);

    if (sub == 0)
        out[(long long)node * LANES + flane] = acc;
}

extern "C" void kernel_launch(void* const* d_in, const int* in_sizes, int n_in,
                              void* d_out, int out_size)
{
    const void*   edge_index = d_in[0];
    const float4* feat       = (const float4*)d_in[1];
    float4*       out        = (float4*)d_out;

    const int E = in_sizes[1] / D_FEAT;
    const int N = out_size / D_FEAT;

    const int p1_threads = (E + KEYS_PER_THREAD - 1) / KEYS_PER_THREAD;
    build_offsets_kernel<<<(p1_threads + 255) / 256, 256>>>(edge_index, E, N);

    const int grid = (N + WARPS_PER_BLOCK - 1) / WARPS_PER_BLOCK;
    edgewise_reduce_kernel<<<grid, BLOCK_THREADS>>>(feat, out, N);
}

// round 10
// speedup vs baseline: 1.2740x; 1.1164x over previous
#include <cuda_runtime.h>

// EdgewiseReduce: out[n, :] = sum_{e : edge_center[e] == n} edge_feat[e, :]
// edge_center (= edge_index[0]) is SORTED ascending.
//
// Pass 1 (build_offsets): vectorized (4 keys/thread) CSR row_offsets;
//   prev-key via __shfl_up (lane 0 loads one extra scalar).
// Pass 2 (reduce): ONE WARP PER NODE, 64-thread CTAs. Lanes 0-15 / 16-31 hold
//   two edges' float4 rows. Inner loop = UNPREDICATED full batches of 8
//   LDG.128 into distinct registers (true MLP=8; predication previously forced
//   ptxas into register-reuse serialization, regs=34) + ONE predicated
//   remainder batch. __ldcs streaming loads (no reuse -> evict-first).
//   16-wide shfl combine, single coalesced 256B store. No atomics, no memset.
//
// Inputs (metadata order):
//   d_in[0] = edge_index  [2, E]  int64 (or int32; runtime-detected)
//   d_in[1] = edge_feat   [E, 64] float32
//   d_in[2] = node_types  [N, 1]
// Output: [N, 64] float32

#define D_FEAT 64
#define LANES 16
#define BLOCK_THREADS 64                       // 2 warps per CTA
#define WARPS_PER_BLOCK (BLOCK_THREADS / 32)
#define KEYS_PER_THREAD 4
#define STEPS 8                     // edges per batch = 2 * STEPS = 16
#define MAX_NODES_P1 (1 << 21)

__device__ int g_offsets[MAX_NODES_P1];

// ---------------- Pass 1: CSR offsets from sorted keys ---------------------
__global__ void __launch_bounds__(256)
build_offsets_kernel(const void* __restrict__ edge_index, int E, int N)
{
    // dtype detection: an int64 read of an int32 buffer fuses two indices ->
    // value >= 2^32 >> N with overwhelming probability across 3 probes.
    __shared__ int s_is64;
    if (threadIdx.x == 0) {
        const long long* q = (const long long*)edge_index;
        unsigned long long v0 = (unsigned long long)q[E / 3];
        unsigned long long v1 = (unsigned long long)q[E / 2];
        unsigned long long v2 = (unsigned long long)q[E - 1];
        unsigned long long nn = (unsigned long long)N;
        s_is64 = (v0 < nn && v1 < nn && v2 < nn) ? 1 : 0;
    }
    __syncthreads();
    const bool is64 = (s_is64 != 0);

    const long long* __restrict__ p64 = (const long long*)edge_index;
    const int*       __restrict__ p32 = (const int*)edge_index;

    const int base = (blockIdx.x * blockDim.x + threadIdx.x) * KEYS_PER_THREAD;
    const int lane = threadIdx.x & 31;

    int k[KEYS_PER_THREAD];
    int nvalid = 0;
    if (base < E) {
        if (base + KEYS_PER_THREAD <= E) {
            nvalid = KEYS_PER_THREAD;
            if (is64) {
                longlong2 v0 = ((const longlong2*)p64)[(base >> 1) + 0];
                longlong2 v1 = ((const longlong2*)p64)[(base >> 1) + 1];
                k[0] = (int)v0.x; k[1] = (int)v0.y; k[2] = (int)v1.x; k[3] = (int)v1.y;
            } else {
                int4 v = ((const int4*)p32)[base >> 2];
                k[0] = v.x; k[1] = v.y; k[2] = v.z; k[3] = v.w;
            }
        } else {
            nvalid = E - base;
            #pragma unroll
            for (int j = 0; j < KEYS_PER_THREAD; ++j)
                if (j < nvalid) k[j] = is64 ? (int)p64[base + j] : p32[base + j];
        }
    }
    for (int j = nvalid; j < KEYS_PER_THREAD; ++j) k[j] = 0;  // shfl payload

    int prev = __shfl_up_sync(0xffffffffu, k[KEYS_PER_THREAD - 1], 1);
    if (lane == 0 && base > 0 && base <= E)
        prev = is64 ? (int)p64[base - 1] : p32[base - 1];
    if (base == 0) prev = -1;

    if (base >= E) return;

    #pragma unroll
    for (int j = 0; j < KEYS_PER_THREAD; ++j) {
        if (j < nvalid) {
            const int c = k[j];
            for (int n = prev + 1; n <= c; ++n) g_offsets[n] = base + j;
            prev = c;
        }
    }

    if (base + nvalid == E) {
        for (int n = prev + 1; n <= N; ++n) g_offsets[n] = E;
    }
}

// ---------------- Pass 2: warp-per-node, unpredicated full batches ----------
__global__ void __launch_bounds__(BLOCK_THREADS)
edgewise_reduce_kernel(const float4* __restrict__ feat,   // [E * LANES]
                       float4* __restrict__ out,          // [N * LANES]
                       int N)
{
    const int lane  = threadIdx.x & 31;
    const int sub   = lane >> 4;        // which edge of the pair (0/1)
    const int flane = lane & (LANES - 1);
    const int node  = blockIdx.x * WARPS_PER_BLOCK + (threadIdx.x >> 5);
    if (node >= N) return;

    const int start = g_offsets[node];
    const int end   = g_offsets[node + 1];

    float4 acc = make_float4(0.f, 0.f, 0.f, 0.f);
    int e = start + sub;

    // Full batches: 8 UNPREDICATED streaming LDG.128 into distinct registers.
    #pragma unroll 1
    while (e + 2 * (STEPS - 1) < end) {
        float4 v[STEPS];
        #pragma unroll
        for (int i = 0; i < STEPS; ++i)
            v[i] = __ldcs(&feat[(long long)(e + 2 * i) * LANES + flane]);
        #pragma unroll
        for (int i = 0; i < STEPS; ++i) {
            acc.x += v[i].x; acc.y += v[i].y; acc.z += v[i].z; acc.w += v[i].w;
        }
        e += 2 * STEPS;
    }

    // Single predicated remainder batch (covers all remaining edges).
    #pragma unroll
    for (int i = 0; i < STEPS; ++i) {
        const int idx = e + 2 * i;
        if (idx < end) {
            float4 v = __ldcs(&feat[(long long)idx * LANES + flane]);
            acc.x += v.x; acc.y += v.y; acc.z += v.z; acc.w += v.w;
        }
    }

    // Combine the two edge-halves: lane l += lane l+16.
    acc.x += __shfl_down_sync(0xffffffffu, acc.x, 16);
    acc.y += __shfl_down_sync(0xffffffffu, acc.y, 16);
    acc.z += __shfl_down_sync(0xffffffffu, acc.z, 16);
    acc.w += __shfl_down_sync(0xffffffffu, acc.w, 16);

    if (sub == 0)
        out[(long long)node * LANES + flane] = acc;
}

extern "C" void kernel_launch(void* const* d_in, const int* in_sizes, int n_in,
                              void* d_out, int out_size)
{
    const void*   edge_index = d_in[0];
    const float4* feat       = (const float4*)d_in[1];
    float4*       out        = (float4*)d_out;

    const int E = in_sizes[1] / D_FEAT;
    const int N = out_size / D_FEAT;

    const int p1_threads = (E + KEYS_PER_THREAD - 1) / KEYS_PER_THREAD;
    build_offsets_kernel<<<(p1_threads + 255) / 256, 256>>>(edge_index, E, N);

    const int grid = (N + WARPS_PER_BLOCK - 1) / WARPS_PER_BLOCK;
    edgewise_reduce_kernel<<<grid, BLOCK_THREADS>>>(feat, out, N);
}